// round 1
// baseline (speedup 1.0000x reference)
#include <cuda_runtime.h>
#include <cuda_bf16.h>
#include <stdint.h>

// Problem constants
#define DIMS   128          // embedding dim (C)
#define KCODES 512          // num embeddings
#define NB     32           // batch
#define HW     4096         // 64*64
#define NROWS  131072       // NB*HW
#define ZSTRB  524288       // DIMS*HW (per-batch stride in z)

// Output layout (floats, concatenated tuple)
#define OFF_Q    ((size_t)0)
#define OFF_LOSS ((size_t)16777216)
#define OFF_IDX  ((size_t)16777217)
#define OFF_EMB  ((size_t)16908289)
#define OFF_CS   ((size_t)16973825)
#define OFF_EA   ((size_t)16974337)

// Main kernel tiling
#define MTILE   128         // rows per block
#define KCHUNK  256         // codes per shared chunk (2 chunks)
#define SMEM_MAIN (65536 + 131072 + 1024 + 1024 + 512)  // xs + es + enorm + minbuf + idxs

// Device scratch (static allocation — allowed)
__device__ float g_embed_sum[DIMS * KCODES];
__device__ int   g_counts[KCODES];
__device__ float g_loss;
__device__ float g_enorm[KCODES];
__device__ float g_cs[KCODES];
__device__ int   g_idx[NROWS];

// ---------- helpers ----------
__device__ __forceinline__ unsigned fenc(float f) {
    unsigned u = __float_as_uint(f);
    return (u & 0x80000000u) ? ~u : (u | 0x80000000u);
}
__device__ __forceinline__ float fdec(unsigned e) {
    return (e & 0x80000000u) ? __uint_as_float(e ^ 0x80000000u)
                             : __uint_as_float(~e);
}
__device__ __forceinline__ void unpack2(unsigned long long v, float& lo, float& hi) {
    asm("mov.b64 {%0,%1}, %2;" : "=f"(lo), "=f"(hi) : "l"(v));
}

// ---------- K0: zero scratch ----------
__global__ void k_zero() {
    int i = blockIdx.x * 256 + threadIdx.x;          // grid 256 x 256 = 65536
    g_embed_sum[i] = 0.f;
    if (i < KCODES) g_counts[i] = 0;
    if (i == 0) g_loss = 0.f;
}

// ---------- K0b: per-code squared norms ----------
__global__ void k_enorm(const float* __restrict__ emb) {
    int k = blockIdx.x * 256 + threadIdx.x;          // grid 2 x 256 = 512
    float s = 0.f;
    #pragma unroll 8
    for (int d = 0; d < DIMS; d++) {
        float e = emb[d * KCODES + k];               // coalesced over k
        s = fmaf(e, e, s);
    }
    g_enorm[k] = s;
}

// ---------- K1: fused distance GEMM + argmin + gather + loss + histogram ----------
__global__ __launch_bounds__(256, 1)
void k_main(const float* __restrict__ z, const float* __restrict__ emb,
            float* __restrict__ out) {
    extern __shared__ float sm[];
    float* xs   = sm;                                  // [128][128]  64 KB
    float* es   = sm + 16384;                          // [128][256] 128 KB
    float* en_s = es + 32768;                          // [256]
    unsigned long long* minbuf = (unsigned long long*)(en_s + 256);  // [128]
    int* idxs = (int*)(minbuf + 128);                  // [128]
    __shared__ float lbuf;

    const int tid = threadIdx.x;
    const int tr = tid & 15;        // row group  (rows tr + 16*jr, jr=0..7)
    const int tc = tid >> 4;        // code group (codes 2*tc + 32*jc (+1), jc=0..7)
    const int blk = blockIdx.x;
    const int b  = blk >> 5;
    const int s0 = (blk & 31) << 7;

    const float* zb = z + (size_t)b * ZSTRB + s0;
    // load x tile [d][r]
    for (int i = tid; i < 16384; i += 256) {
        int d = i >> 7, r = i & 127;
        xs[i] = zb[(size_t)d * HW + r];
    }
    if (tid < 128) minbuf[tid] = 0xFFFFFFFFFFFFFFFFULL;
    if (tid == 0)  lbuf = 0.f;

    const float* xcol = xs + tr;
    const float* ecol = es + 2 * tc;

    for (int c = 0; c < 2; ++c) {
        __syncthreads();
        const int kc0 = c << 8;
        for (int i = tid; i < 32768; i += 256) {
            int d = i >> 8, kk = i & 255;
            es[i] = emb[d * KCODES + kc0 + kk];
        }
        en_s[tid] = g_enorm[kc0 + tid];
        __syncthreads();

        unsigned long long acc[8][8];
        #pragma unroll
        for (int jr = 0; jr < 8; jr++)
            #pragma unroll
            for (int jc = 0; jc < 8; jc++) acc[jr][jc] = 0ULL;

        #pragma unroll 2
        for (int d = 0; d < DIMS; ++d) {
            unsigned long long xv[8], ev[8];
            #pragma unroll
            for (int jr = 0; jr < 8; jr++) {
                float x = xcol[d * 128 + 16 * jr];
                asm("mov.b64 %0, {%1,%1};" : "=l"(xv[jr]) : "f"(x));
            }
            #pragma unroll
            for (int jc = 0; jc < 8; jc++)
                ev[jc] = *reinterpret_cast<const unsigned long long*>(&ecol[d * 256 + 32 * jc]);
            #pragma unroll
            for (int jr = 0; jr < 8; jr++)
                #pragma unroll
                for (int jc = 0; jc < 8; jc++)
                    asm("fma.rn.f32x2 %0, %1, %2, %0;"
                        : "+l"(acc[jr][jc]) : "l"(xv[jr]), "l"(ev[jc]));
        }

        // per-thread argmin over its 16 codes, then shared atomicMin per row
        #pragma unroll
        for (int jr = 0; jr < 8; jr++) {
            unsigned long long bkey = 0xFFFFFFFFFFFFFFFFULL;
            #pragma unroll
            for (int jc = 0; jc < 8; jc++) {
                float d0, d1;
                unpack2(acc[jr][jc], d0, d1);
                float e0 = en_s[2 * tc + 32 * jc];
                float e1 = en_s[2 * tc + 32 * jc + 1];
                float dist0 = fmaf(-2.f, d0, e0);
                float dist1 = fmaf(-2.f, d1, e1);
                unsigned c0 = (unsigned)(kc0 + 2 * tc + 32 * jc);
                unsigned long long k0 = ((unsigned long long)fenc(dist0) << 32) | c0;
                unsigned long long k1 = ((unsigned long long)fenc(dist1) << 32) | (c0 + 1u);
                unsigned long long kk = k0 < k1 ? k0 : k1;
                if (kk < bkey) bkey = kk;
            }
            atomicMin(&minbuf[tr + 16 * jr], bkey);
        }
    }
    __syncthreads();

    // per-row epilogue: decode argmin, loss, index outputs, histogram
    if (tid < 128) {
        unsigned long long key = minbuf[tid];
        int code = (int)(key & 0xFFFFFFFFu);
        float dmin = fdec((unsigned)(key >> 32));
        float xn = 0.f;
        #pragma unroll 8
        for (int d = 0; d < DIMS; d++) {
            float v = xs[d * 128 + tid];
            xn = fmaf(v, v, xn);
        }
        atomicAdd(&lbuf, xn + dmin);          // ||x-e||^2 via expansion
        idxs[tid] = code;
        int ng = blk * MTILE + tid;
        out[OFF_IDX + ng] = (float)code;
        g_idx[ng] = code;
        atomicAdd(&g_counts[code], 1);
    }
    __syncthreads();
    if (tid == 0) atomicAdd(&g_loss, lbuf);

    // gather quantized and write back in [B,D,H,W] layout (coalesced over r)
    for (int i = tid; i < 16384; i += 256) {
        int d = i >> 7, r = i & 127;
        out[OFF_Q + (size_t)b * ZSTRB + (size_t)d * HW + s0 + r] =
            emb[d * KCODES + idxs[r]];
    }
}

// ---------- K2: cluster-size EMA + Laplace smoothing ----------
__global__ void k_stats(const float* __restrict__ cs_in, float* __restrict__ out) {
    __shared__ float sh[KCODES];
    int k = threadIdx.x;                              // 512 threads
    float ncs = cs_in[k] * 0.99f + 0.01f * (float)g_counts[k];
    out[OFF_CS + k] = ncs;
    sh[k] = ncs;
    __syncthreads();
    for (int s = 256; s > 0; s >>= 1) {
        if (k < s) sh[k] += sh[k + s];
        __syncthreads();
    }
    float n = fmaxf(sh[0], 1e-5f);
    float c = (ncs + 1e-5f) / (n + KCODES * 1e-5f) * n;
    g_cs[k] = c;
}

// ---------- K4: embed_sum via d-plane pass with shared privatized bins ----------
__global__ void k_esum(const float* __restrict__ z) {
    __shared__ float accs[KCODES];
    const int d = blockIdx.x;       // 0..127
    const int c = blockIdx.y;       // 0..31 (== batch index: 4096 rows each)
    const int tid = threadIdx.x;    // 256
    accs[tid] = 0.f;
    accs[tid + 256] = 0.f;
    __syncthreads();
    const float* zp = z + (size_t)c * ZSTRB + (size_t)d * HW;
    const int* ip = g_idx + c * HW;
    for (int i = tid; i < HW; i += 256)
        atomicAdd(&accs[ip[i]], zp[i]);               // z read coalesced
    __syncthreads();
    float v0 = accs[tid], v1 = accs[tid + 256];
    if (v0 != 0.f) atomicAdd(&g_embed_sum[d * KCODES + tid], v0);
    if (v1 != 0.f) atomicAdd(&g_embed_sum[d * KCODES + tid + 256], v1);
}

// ---------- K5: finalize embed_avg EMA, new embedding, loss ----------
__global__ void k_final(const float* __restrict__ ea_in, float* __restrict__ out) {
    int i = blockIdx.x * 256 + threadIdx.x;           // grid 256 x 256 = 65536
    float es = g_embed_sum[i];
    float ea = ea_in[i] * 0.99f + 0.01f * es;
    out[OFF_EA + i] = ea;
    out[OFF_EMB + i] = ea / g_cs[i & (KCODES - 1)];
    if (i == 0) out[OFF_LOSS] = 1.25f * g_loss * (1.f / 16777216.f);
}

extern "C" void kernel_launch(void* const* d_in, const int* in_sizes, int n_in,
                              void* d_out, int out_size) {
    const float* z   = (const float*)d_in[0];
    const float* emb = (const float*)d_in[1];
    const float* cs  = (const float*)d_in[2];
    const float* ea  = (const float*)d_in[3];
    float* out = (float*)d_out;

    cudaFuncSetAttribute(k_main, cudaFuncAttributeMaxDynamicSharedMemorySize, SMEM_MAIN);

    k_zero<<<256, 256>>>();
    k_enorm<<<2, 256>>>(emb);
    k_main<<<1024, 256, SMEM_MAIN>>>(z, emb, out);
    k_stats<<<1, 512>>>(cs, out);
    k_esum<<<dim3(128, 32), 256>>>(z);
    k_final<<<256, 256>>>(ea, out);
}